// round 2
// baseline (speedup 1.0000x reference)
#include <cuda_runtime.h>
#include <float.h>

// ---------------- problem-size upper bounds (fixed by the dataset) ----------
#define NMAX  100000
#define ESMAX 1000000
#define GMAXC 128

// ---------------- static device scratch (no runtime allocation) -------------
__device__ __align__(256) float    g_bufA[NMAX * 128];   // h1, then hw2
__device__ __align__(256) float    g_bufB[NMAX * 128];   // hw1, then agg2/h3
__device__ __align__(256) float    g_bufC[NMAX * 128];   // agg1 (pre-relu h2)
__device__ __align__(256) float    g_deg [NMAX];
__device__ __align__(256) float    g_dinv[NMAX];
__device__ __align__(256) float    g_logits[ESMAX];
__device__ __align__(256) unsigned g_gmax[GMAXC];
__device__ __align__(256) float    g_gsum[GMAXC];

// ---------------- helpers ----------------------------------------------------
__device__ __forceinline__ unsigned fenc(float f) {
    unsigned u = __float_as_uint(f);
    return (u & 0x80000000u) ? ~u : (u | 0x80000000u);
}
__device__ __forceinline__ float fdec(unsigned v) {
    unsigned u = (v & 0x80000000u) ? (v & 0x7fffffffu) : ~v;
    return __uint_as_float(u);
}
__device__ __forceinline__ float warpMaxf(float v) {
    #pragma unroll
    for (int o = 16; o; o >>= 1) v = fmaxf(v, __shfl_xor_sync(0xffffffffu, v, o));
    return v;
}
__device__ __forceinline__ float warpSumf(float v) {
    #pragma unroll
    for (int o = 16; o; o >>= 1) v += __shfl_xor_sync(0xffffffffu, v, o);
    return v;
}

// ---------------- init / degree / dinv ---------------------------------------
__global__ void init_kernel(float* __restrict__ deg, unsigned* __restrict__ gmax,
                            float* __restrict__ gsum, int N, int G) {
    int i = blockIdx.x * blockDim.x + threadIdx.x;
    if (i < N) deg[i] = 1.0f;                 // self-loop weight
    if (i < G) { gmax[i] = 0x00800000u;       // fenc(-FLT_MAX)
                 gsum[i] = 0.0f; }
}

__global__ void deg_kernel(float* __restrict__ deg, const int* __restrict__ col,
                           const float* __restrict__ w, int E) {
    int i = blockIdx.x * blockDim.x + threadIdx.x;
    if (i < E) atomicAdd(&deg[col[i]], w[i]);
}

__global__ void dinv_kernel(const float* __restrict__ deg, float* __restrict__ dinv, int N) {
    int i = blockIdx.x * blockDim.x + threadIdx.x;
    if (i < N) {
        float d = deg[i];
        dinv[i] = (d > 0.0f) ? rsqrtf(d) : 0.0f;
    }
}

// ---------------- tiled per-node dense layer: out = (relu?)in @ W (+bias) ----
// block = 256 threads, tile = 64 nodes x 64 output cols, K chunked by 64.
__global__ __launch_bounds__(256)
void node_linear_kernel(const float* __restrict__ in, const float* __restrict__ W,
                        const float* __restrict__ bias, float* __restrict__ out,
                        int N, int IN, int OUT, int reluIn) {
    __shared__ float xs[64 * 65];
    __shared__ __align__(16) float ws[64 * 64];

    int t = threadIdx.x;
    int nodeBase = blockIdx.x * 64;
    int colBase  = blockIdx.y * 64;
    int tx = t & 15;       // col group: 4 cols at tx*4
    int ty = t >> 4;       // node group: 4 nodes at ty*4

    float4 acc0 = {0,0,0,0}, acc1 = {0,0,0,0}, acc2 = {0,0,0,0}, acc3 = {0,0,0,0};

    int nChunks = IN >> 6;
    for (int kc = 0; kc < nChunks; kc++) {
        for (int i = t; i < 64 * 64; i += 256) {
            int nn = i >> 6, kk = i & 63;
            int node = nodeBase + nn;
            float v = 0.0f;
            if (node < N) v = in[(long)node * IN + kc * 64 + kk];
            if (reluIn) v = fmaxf(v, 0.0f);
            xs[nn * 65 + kk] = v;
        }
        for (int i = t; i < 64 * 64; i += 256) {
            int kk = i >> 6, cc = i & 63;
            ws[i] = W[(long)(kc * 64 + kk) * OUT + colBase + cc];
        }
        __syncthreads();

        #pragma unroll 8
        for (int k = 0; k < 64; k++) {
            float4 wv = *(const float4*)&ws[k * 64 + tx * 4];
            float x0 = xs[(ty * 4 + 0) * 65 + k];
            float x1 = xs[(ty * 4 + 1) * 65 + k];
            float x2 = xs[(ty * 4 + 2) * 65 + k];
            float x3 = xs[(ty * 4 + 3) * 65 + k];
            acc0.x = fmaf(x0, wv.x, acc0.x); acc0.y = fmaf(x0, wv.y, acc0.y);
            acc0.z = fmaf(x0, wv.z, acc0.z); acc0.w = fmaf(x0, wv.w, acc0.w);
            acc1.x = fmaf(x1, wv.x, acc1.x); acc1.y = fmaf(x1, wv.y, acc1.y);
            acc1.z = fmaf(x1, wv.z, acc1.z); acc1.w = fmaf(x1, wv.w, acc1.w);
            acc2.x = fmaf(x2, wv.x, acc2.x); acc2.y = fmaf(x2, wv.y, acc2.y);
            acc2.z = fmaf(x2, wv.z, acc2.z); acc2.w = fmaf(x2, wv.w, acc2.w);
            acc3.x = fmaf(x3, wv.x, acc3.x); acc3.y = fmaf(x3, wv.y, acc3.y);
            acc3.z = fmaf(x3, wv.z, acc3.z); acc3.w = fmaf(x3, wv.w, acc3.w);
        }
        __syncthreads();
    }

    float4 bv = {0,0,0,0};
    if (bias) bv = *(const float4*)&bias[colBase + tx * 4];
    float4 accs[4] = {acc0, acc1, acc2, acc3};
    #pragma unroll
    for (int i = 0; i < 4; i++) {
        int node = nodeBase + ty * 4 + i;
        if (node < N) {
            float4 r;
            r.x = accs[i].x + bv.x; r.y = accs[i].y + bv.y;
            r.z = accs[i].z + bv.z; r.w = accs[i].w + bv.w;
            *(float4*)&out[(long)node * OUT + colBase + tx * 4] = r;
        }
    }
}

// ---------------- GCN aggregation: self-loop init + edge scatter -------------
__global__ void agg_init_kernel(const float* __restrict__ hw, const float* __restrict__ dinv,
                                const float* __restrict__ bias, float* __restrict__ agg,
                                int N, int F) {
    int idx = blockIdx.x * blockDim.x + threadIdx.x;
    if (idx < N * F) {
        int n = idx / F, j = idx - n * F;
        float di = dinv[n];
        agg[idx] = bias[j] + hw[idx] * di * di;
    }
}

template <int F>
__global__ void agg_edge_kernel(const float* __restrict__ hw, const float* __restrict__ dinv,
                                const int* __restrict__ row, const int* __restrict__ col,
                                const float* __restrict__ w, float* __restrict__ agg, int E) {
    int gt = blockIdx.x * blockDim.x + threadIdx.x;
    int e = gt >> 5, lane = gt & 31;
    if (e >= E) return;
    int r = row[e], c = col[e];
    float nrm = dinv[r] * w[e] * dinv[c];
    if (F == 128) {
        float4 v = ((const float4*)(hw + (long)r * 128))[lane];
        float* dst = agg + (long)c * 128 + lane * 4;
        atomicAdd(dst + 0, v.x * nrm); atomicAdd(dst + 1, v.y * nrm);
        atomicAdd(dst + 2, v.z * nrm); atomicAdd(dst + 3, v.w * nrm);
    } else {
        float2 v = ((const float2*)(hw + (long)r * 64))[lane];
        float* dst = agg + (long)c * 64 + lane * 2;
        atomicAdd(dst + 0, v.x * nrm); atomicAdd(dst + 1, v.y * nrm);
    }
}

// ---------------- per-pair MLP (128 -> 64 -> 32 -> 1) + per-graph max --------
__global__ __launch_bounds__(256)
void pair_mlp_kernel(const float* __restrict__ h3, const int* __restrict__ pair,
                     const int* __restrict__ eg,
                     const float* __restrict__ Wa, const float* __restrict__ ba,
                     const float* __restrict__ Wb, const float* __restrict__ bb,
                     const float* __restrict__ Wc, const float* __restrict__ bc,
                     float* __restrict__ logits, unsigned* __restrict__ gmax, int ES) {
    __shared__ float sWa[128 * 64];   // 32 KB
    __shared__ float sWb[64 * 32];    //  8 KB
    __shared__ float sWc[32], sba[64], sbb[32];
    __shared__ float sbc;

    int t = threadIdx.x;
    for (int i = t; i < 128 * 64; i += 256) sWa[i] = Wa[i];
    for (int i = t; i < 64 * 32;  i += 256) sWb[i] = Wb[i];
    if (t < 64) sba[t] = ba[t];
    if (t < 32) { sWc[t] = Wc[t]; sbb[t] = bb[t]; }
    if (t == 0) sbc = bc[0];
    __syncthreads();

    int i = blockIdx.x * 256 + t;
    bool active = (i < ES);
    float logit = -FLT_MAX;
    int g = 0;

    if (active) {
        int p0 = pair[i];
        int p1 = pair[ES + i];
        g = eg[i];

        float s1[64];
        #pragma unroll
        for (int j = 0; j < 64; j++) s1[j] = sba[j];

        const float4* hv = (const float4*)h3;
        #pragma unroll 1
        for (int half = 0; half < 2; half++) {
            long rb = (long)(half ? p1 : p0) * 16;
            const float* wb = sWa + half * 64 * 64;
            #pragma unroll 1
            for (int kq = 0; kq < 16; kq++) {
                float4 xv = hv[rb + kq];
                const float* wr = wb + kq * 4 * 64;
                #pragma unroll
                for (int j = 0; j < 64; j++) s1[j] = fmaf(xv.x, wr[j],       s1[j]);
                #pragma unroll
                for (int j = 0; j < 64; j++) s1[j] = fmaf(xv.y, wr[64 + j],  s1[j]);
                #pragma unroll
                for (int j = 0; j < 64; j++) s1[j] = fmaf(xv.z, wr[128 + j], s1[j]);
                #pragma unroll
                for (int j = 0; j < 64; j++) s1[j] = fmaf(xv.w, wr[192 + j], s1[j]);
            }
        }

        float s2[32];
        #pragma unroll
        for (int q = 0; q < 32; q++) s2[q] = sbb[q];
        #pragma unroll
        for (int j = 0; j < 64; j++) {
            float v = fmaxf(s1[j], 0.0f);
            #pragma unroll
            for (int q = 0; q < 32; q++) s2[q] = fmaf(v, sWb[j * 32 + q], s2[q]);
        }
        float acc = sbc;
        #pragma unroll
        for (int q = 0; q < 32; q++) acc = fmaf(fmaxf(s2[q], 0.0f), sWc[q], acc);
        logit = acc;
        logits[i] = logit;
    }

    // per-graph max: edge_graph is sorted -> most warps are single-graph
    bool fullWarp = ((blockIdx.x * 256 + (t & ~31)) + 31) < ES;
    int g0 = __shfl_sync(0xffffffffu, g, 0);
    int g31 = __shfl_sync(0xffffffffu, g, 31);
    if (fullWarp && g0 == g31) {
        float m = warpMaxf(logit);
        if ((t & 31) == 0) atomicMax(&gmax[g0], fenc(m));
    } else if (active) {
        atomicMax(&gmax[g], fenc(logit));
    }
}

// ---------------- segment softmax: exp + sum, then divide --------------------
__global__ void softmax_exp_kernel(float* __restrict__ logits, const int* __restrict__ eg,
                                   const unsigned* __restrict__ gmax, float* __restrict__ gsum,
                                   int ES) {
    int t = threadIdx.x;
    int i = blockIdx.x * blockDim.x + t;
    bool active = (i < ES);
    float e = 0.0f;
    int g = 0;
    if (active) {
        g = eg[i];
        e = expf(logits[i] - fdec(gmax[g]));
        logits[i] = e;
    }
    bool fullWarp = ((blockIdx.x * blockDim.x + (t & ~31)) + 31) < ES;
    int g0 = __shfl_sync(0xffffffffu, g, 0);
    int g31 = __shfl_sync(0xffffffffu, g, 31);
    if (fullWarp && g0 == g31) {
        float s = warpSumf(e);
        if ((t & 31) == 0) atomicAdd(&gsum[g0], s);
    } else if (active) {
        atomicAdd(&gsum[g], e);
    }
}

__global__ void softmax_div_kernel(float* __restrict__ out, const float* __restrict__ logits,
                                   const int* __restrict__ eg, const float* __restrict__ gsum,
                                   int ES) {
    int i = blockIdx.x * blockDim.x + threadIdx.x;
    if (i < ES) out[i] = logits[i] / gsum[eg[i]];
}

// ---------------- launcher ----------------------------------------------------
extern "C" void kernel_launch(void* const* d_in, const int* in_sizes, int n_in,
                              void* d_out, int out_size) {
    const float* x  = (const float*)d_in[0];
    const int*   ei = (const int*)  d_in[1];
    const float* ew = (const float*)d_in[2];
    const int*   pi = (const int*)  d_in[3];
    const int*   eg = (const int*)  d_in[4];
    // num_graphs may or may not be materialized as a 1-element tensor
    int base = (in_sizes[5] == 1) ? 6 : 5;
    const float* Wproj = (const float*)d_in[base + 0];
    const float* bproj = (const float*)d_in[base + 1];
    const float* W1    = (const float*)d_in[base + 2];
    const float* b1    = (const float*)d_in[base + 3];
    const float* W2    = (const float*)d_in[base + 4];
    const float* b2    = (const float*)d_in[base + 5];
    const float* Wa    = (const float*)d_in[base + 6];
    const float* ba    = (const float*)d_in[base + 7];
    const float* Wb    = (const float*)d_in[base + 8];
    const float* bb    = (const float*)d_in[base + 9];
    const float* Wc    = (const float*)d_in[base + 10];
    const float* bc    = (const float*)d_in[base + 11];

    int N  = in_sizes[0] / 64;
    int E  = in_sizes[2];
    int ES = in_sizes[4];
    const int G = GMAXC;

    float *bufA, *bufB, *bufC, *deg, *dinv, *logits, *gsum;
    unsigned* gmax;
    cudaGetSymbolAddress((void**)&bufA,   g_bufA);
    cudaGetSymbolAddress((void**)&bufB,   g_bufB);
    cudaGetSymbolAddress((void**)&bufC,   g_bufC);
    cudaGetSymbolAddress((void**)&deg,    g_deg);
    cudaGetSymbolAddress((void**)&dinv,   g_dinv);
    cudaGetSymbolAddress((void**)&logits, g_logits);
    cudaGetSymbolAddress((void**)&gmax,   g_gmax);
    cudaGetSymbolAddress((void**)&gsum,   g_gsum);

    const int* rowp = ei;        // edge_index[0]
    const int* colp = ei + E;    // edge_index[1]

    // degree + norm
    init_kernel<<<(N + 255) / 256, 256>>>(deg, gmax, gsum, N, G);
    deg_kernel<<<(E + 255) / 256, 256>>>(deg, colp, ew, E);
    dinv_kernel<<<(N + 255) / 256, 256>>>(deg, dinv, N);

    // h1 = x @ Wproj + bproj           [N,128] -> bufA
    dim3 gA((N + 63) / 64, 2);
    node_linear_kernel<<<gA, 256>>>(x, Wproj, bproj, bufA, N, 64, 128, 0);

    // hw1 = h1 @ W1                    [N,128] -> bufB
    node_linear_kernel<<<gA, 256>>>(bufA, W1, nullptr, bufB, N, 128, 128, 0);

    // agg1 = b1 + self + edge scatter  -> bufC
    agg_init_kernel<<<(N * 128 + 255) / 256, 256>>>(bufB, dinv, b1, bufC, N, 128);
    agg_edge_kernel<128><<<(E * 32 + 255) / 256, 256>>>(bufB, dinv, rowp, colp, ew, bufC, E);

    // hw2 = relu(agg1) @ W2            [N,64] -> bufA
    dim3 gB((N + 63) / 64, 1);
    node_linear_kernel<<<gB, 256>>>(bufC, W2, nullptr, bufA, N, 128, 64, 1);

    // agg2 = b2 + self + edge scatter  -> bufB  (= h3)
    agg_init_kernel<<<(N * 64 + 255) / 256, 256>>>(bufA, dinv, b2, bufB, N, 64);
    agg_edge_kernel<64><<<(E * 32 + 255) / 256, 256>>>(bufA, dinv, rowp, colp, ew, bufB, E);

    // pair MLP + segment softmax
    pair_mlp_kernel<<<(ES + 255) / 256, 256>>>(bufB, pi, eg, Wa, ba, Wb, bb, Wc, bc,
                                               logits, gmax, ES);
    softmax_exp_kernel<<<(ES + 255) / 256, 256>>>(logits, eg, gmax, gsum, ES);
    softmax_div_kernel<<<(ES + 255) / 256, 256>>>((float*)d_out, logits, eg, gsum, ES);
}

// round 3
// speedup vs baseline: 1.7761x; 1.7761x over previous
#include <cuda_runtime.h>
#include <float.h>

// ---------------- problem-size upper bounds (fixed by the dataset) ----------
#define NMAX  100000
#define ESMAX 1000000
#define GMAXC 128

// ---------------- static device scratch (no runtime allocation) -------------
__device__ __align__(256) float    g_bufA[NMAX * 128];   // h1, hw2, then u0
__device__ __align__(256) float    g_bufB[NMAX * 128];   // hw1, then agg2/h3
__device__ __align__(256) float    g_bufC[NMAX * 128];   // agg1, then u1
__device__ __align__(256) float    g_deg [NMAX];
__device__ __align__(256) float    g_dinv[NMAX];
__device__ __align__(256) float    g_logits[ESMAX];
__device__ __align__(256) unsigned g_gmax[GMAXC];
__device__ __align__(256) float    g_gsum[GMAXC];

// ---------------- helpers ----------------------------------------------------
__device__ __forceinline__ unsigned fenc(float f) {
    unsigned u = __float_as_uint(f);
    return (u & 0x80000000u) ? ~u : (u | 0x80000000u);
}
__device__ __forceinline__ float fdec(unsigned v) {
    unsigned u = (v & 0x80000000u) ? (v & 0x7fffffffu) : ~v;
    return __uint_as_float(u);
}
__device__ __forceinline__ float warpMaxf(float v) {
    #pragma unroll
    for (int o = 16; o; o >>= 1) v = fmaxf(v, __shfl_xor_sync(0xffffffffu, v, o));
    return v;
}
__device__ __forceinline__ float warpSumf(float v) {
    #pragma unroll
    for (int o = 16; o; o >>= 1) v += __shfl_xor_sync(0xffffffffu, v, o);
    return v;
}
__device__ __forceinline__ void redAdd4(float* dst, float a, float b, float c, float d) {
    asm volatile("red.global.add.v4.f32 [%0], {%1,%2,%3,%4};"
                 :: "l"(dst), "f"(a), "f"(b), "f"(c), "f"(d) : "memory");
}
__device__ __forceinline__ void redAdd2(float* dst, float a, float b) {
    asm volatile("red.global.add.v2.f32 [%0], {%1,%2};"
                 :: "l"(dst), "f"(a), "f"(b) : "memory");
}

// ---------------- init / degree / dinv ---------------------------------------
__global__ void init_kernel(float* __restrict__ deg, unsigned* __restrict__ gmax,
                            float* __restrict__ gsum, int N, int G) {
    int i = blockIdx.x * blockDim.x + threadIdx.x;
    if (i < N) deg[i] = 1.0f;                 // self-loop weight
    if (i < G) { gmax[i] = 0x00800000u;       // fenc(-FLT_MAX)
                 gsum[i] = 0.0f; }
}

__global__ void deg_kernel(float* __restrict__ deg, const int* __restrict__ col,
                           const float* __restrict__ w, int E) {
    int i = blockIdx.x * blockDim.x + threadIdx.x;
    if (i < E) atomicAdd(&deg[col[i]], w[i]);
}

__global__ void dinv_kernel(const float* __restrict__ deg, float* __restrict__ dinv, int N) {
    int i = blockIdx.x * blockDim.x + threadIdx.x;
    if (i < N) {
        float d = deg[i];
        dinv[i] = (d > 0.0f) ? rsqrtf(d) : 0.0f;
    }
}

// ---------------- tiled per-node dense layer: out = (relu?)in @ W (+bias) ----
__global__ __launch_bounds__(256)
void node_linear_kernel(const float* __restrict__ in, const float* __restrict__ W,
                        const float* __restrict__ bias, float* __restrict__ out,
                        int N, int IN, int OUT, int reluIn) {
    __shared__ float xs[64 * 65];
    __shared__ __align__(16) float ws[64 * 64];

    int t = threadIdx.x;
    int nodeBase = blockIdx.x * 64;
    int colBase  = blockIdx.y * 64;
    int tx = t & 15;       // col group: 4 cols at tx*4
    int ty = t >> 4;       // node group: 4 nodes at ty*4

    float4 acc0 = {0,0,0,0}, acc1 = {0,0,0,0}, acc2 = {0,0,0,0}, acc3 = {0,0,0,0};

    int nChunks = IN >> 6;
    for (int kc = 0; kc < nChunks; kc++) {
        for (int i = t; i < 64 * 64; i += 256) {
            int nn = i >> 6, kk = i & 63;
            int node = nodeBase + nn;
            float v = 0.0f;
            if (node < N) v = in[(long)node * IN + kc * 64 + kk];
            if (reluIn) v = fmaxf(v, 0.0f);
            xs[nn * 65 + kk] = v;
        }
        for (int i = t; i < 64 * 64; i += 256) {
            int kk = i >> 6, cc = i & 63;
            ws[i] = W[(long)(kc * 64 + kk) * OUT + colBase + cc];
        }
        __syncthreads();

        #pragma unroll 8
        for (int k = 0; k < 64; k++) {
            float4 wv = *(const float4*)&ws[k * 64 + tx * 4];
            float x0 = xs[(ty * 4 + 0) * 65 + k];
            float x1 = xs[(ty * 4 + 1) * 65 + k];
            float x2 = xs[(ty * 4 + 2) * 65 + k];
            float x3 = xs[(ty * 4 + 3) * 65 + k];
            acc0.x = fmaf(x0, wv.x, acc0.x); acc0.y = fmaf(x0, wv.y, acc0.y);
            acc0.z = fmaf(x0, wv.z, acc0.z); acc0.w = fmaf(x0, wv.w, acc0.w);
            acc1.x = fmaf(x1, wv.x, acc1.x); acc1.y = fmaf(x1, wv.y, acc1.y);
            acc1.z = fmaf(x1, wv.z, acc1.z); acc1.w = fmaf(x1, wv.w, acc1.w);
            acc2.x = fmaf(x2, wv.x, acc2.x); acc2.y = fmaf(x2, wv.y, acc2.y);
            acc2.z = fmaf(x2, wv.z, acc2.z); acc2.w = fmaf(x2, wv.w, acc2.w);
            acc3.x = fmaf(x3, wv.x, acc3.x); acc3.y = fmaf(x3, wv.y, acc3.y);
            acc3.z = fmaf(x3, wv.z, acc3.z); acc3.w = fmaf(x3, wv.w, acc3.w);
        }
        __syncthreads();
    }

    float4 bv = {0,0,0,0};
    if (bias) bv = *(const float4*)&bias[colBase + tx * 4];
    float4 accs[4] = {acc0, acc1, acc2, acc3};
    #pragma unroll
    for (int i = 0; i < 4; i++) {
        int node = nodeBase + ty * 4 + i;
        if (node < N) {
            float4 r;
            r.x = accs[i].x + bv.x; r.y = accs[i].y + bv.y;
            r.z = accs[i].z + bv.z; r.w = accs[i].w + bv.w;
            *(float4*)&out[(long)node * OUT + colBase + tx * 4] = r;
        }
    }
}

// ---------------- GCN aggregation: self-loop init + edge scatter -------------
__global__ void agg_init_kernel(const float* __restrict__ hw, const float* __restrict__ dinv,
                                const float* __restrict__ bias, float* __restrict__ agg,
                                int N, int F) {
    int idx = blockIdx.x * blockDim.x + threadIdx.x;
    if (idx < N * F) {
        int n = idx / F, j = idx - n * F;
        float di = dinv[n];
        agg[idx] = bias[j] + hw[idx] * di * di;
    }
}

template <int F>
__global__ void agg_edge_kernel(const float* __restrict__ hw, const float* __restrict__ dinv,
                                const int* __restrict__ row, const int* __restrict__ col,
                                const float* __restrict__ w, float* __restrict__ agg, int E) {
    int gt = blockIdx.x * blockDim.x + threadIdx.x;
    int e = gt >> 5, lane = gt & 31;
    if (e >= E) return;
    int r = row[e], c = col[e];
    float nrm = dinv[r] * w[e] * dinv[c];
    if (F == 128) {
        float4 v = ((const float4*)(hw + (long)r * 128))[lane];
        float* dst = agg + (long)c * 128 + lane * 4;
        redAdd4(dst, v.x * nrm, v.y * nrm, v.z * nrm, v.w * nrm);
    } else {
        float2 v = ((const float2*)(hw + (long)r * 64))[lane];
        float* dst = agg + (long)c * 64 + lane * 2;
        redAdd2(dst, v.x * nrm, v.y * nrm);
    }
}

// ---------------- per-pair: gather u0[p0]+u1[p1], relu, 64->32->1, graph max --
__global__ __launch_bounds__(256)
void pair_mlp2_kernel(const float* __restrict__ u0, const float* __restrict__ u1,
                      const int* __restrict__ pair, const int* __restrict__ eg,
                      const float* __restrict__ Wb, const float* __restrict__ bb,
                      const float* __restrict__ Wc, const float* __restrict__ bc,
                      float* __restrict__ logits, unsigned* __restrict__ gmax, int ES) {
    __shared__ __align__(16) float sWb[64 * 32];    // 8 KB
    __shared__ float sWc[32], sbb[32];
    __shared__ float sbc;

    int t = threadIdx.x;
    for (int i = t; i < 64 * 32; i += 256) sWb[i] = Wb[i];
    if (t < 32) { sWc[t] = Wc[t]; sbb[t] = bb[t]; }
    if (t == 0) sbc = bc[0];
    __syncthreads();

    int i = blockIdx.x * 256 + t;
    bool active = (i < ES);
    float logit = -FLT_MAX;
    int g = 0;

    if (active) {
        int p0 = pair[i];
        int p1 = pair[ES + i];
        g = eg[i];

        const float4* a = (const float4*)(u0 + (long)p0 * 64);
        const float4* b = (const float4*)(u1 + (long)p1 * 64);

        float s2[32];
        #pragma unroll
        for (int q = 0; q < 32; q++) s2[q] = sbb[q];

        #pragma unroll 2
        for (int kq = 0; kq < 16; kq++) {
            float4 av = a[kq], bv = b[kq];
            float v0 = fmaxf(av.x + bv.x, 0.0f);
            float v1 = fmaxf(av.y + bv.y, 0.0f);
            float v2 = fmaxf(av.z + bv.z, 0.0f);
            float v3 = fmaxf(av.w + bv.w, 0.0f);
            const float* w0 = sWb + (kq * 4 + 0) * 32;
            const float* w1 = sWb + (kq * 4 + 1) * 32;
            const float* w2 = sWb + (kq * 4 + 2) * 32;
            const float* w3 = sWb + (kq * 4 + 3) * 32;
            #pragma unroll
            for (int q = 0; q < 32; q++) s2[q] = fmaf(v0, w0[q], s2[q]);
            #pragma unroll
            for (int q = 0; q < 32; q++) s2[q] = fmaf(v1, w1[q], s2[q]);
            #pragma unroll
            for (int q = 0; q < 32; q++) s2[q] = fmaf(v2, w2[q], s2[q]);
            #pragma unroll
            for (int q = 0; q < 32; q++) s2[q] = fmaf(v3, w3[q], s2[q]);
        }

        float acc = sbc;
        #pragma unroll
        for (int q = 0; q < 32; q++) acc = fmaf(fmaxf(s2[q], 0.0f), sWc[q], acc);
        logit = acc;
        logits[i] = logit;
    }

    // per-graph max: edge_graph is sorted -> most warps are single-graph
    bool fullWarp = ((blockIdx.x * 256 + (t & ~31)) + 31) < ES;
    int g0 = __shfl_sync(0xffffffffu, g, 0);
    int g31 = __shfl_sync(0xffffffffu, g, 31);
    if (fullWarp && g0 == g31) {
        float m = warpMaxf(logit);
        if ((t & 31) == 0) atomicMax(&gmax[g0], fenc(m));
    } else if (active) {
        atomicMax(&gmax[g], fenc(logit));
    }
}

// ---------------- segment softmax: exp + sum, then divide --------------------
__global__ void softmax_exp_kernel(float* __restrict__ logits, const int* __restrict__ eg,
                                   const unsigned* __restrict__ gmax, float* __restrict__ gsum,
                                   int ES) {
    int t = threadIdx.x;
    int i = blockIdx.x * blockDim.x + t;
    bool active = (i < ES);
    float e = 0.0f;
    int g = 0;
    if (active) {
        g = eg[i];
        e = expf(logits[i] - fdec(gmax[g]));
        logits[i] = e;
    }
    bool fullWarp = ((blockIdx.x * blockDim.x + (t & ~31)) + 31) < ES;
    int g0 = __shfl_sync(0xffffffffu, g, 0);
    int g31 = __shfl_sync(0xffffffffu, g, 31);
    if (fullWarp && g0 == g31) {
        float s = warpSumf(e);
        if ((t & 31) == 0) atomicAdd(&gsum[g0], s);
    } else if (active) {
        atomicAdd(&gsum[g], e);
    }
}

__global__ void softmax_div_kernel(float* __restrict__ out, const float* __restrict__ logits,
                                   const int* __restrict__ eg, const float* __restrict__ gsum,
                                   int ES) {
    int i = blockIdx.x * blockDim.x + threadIdx.x;
    if (i < ES) out[i] = logits[i] / gsum[eg[i]];
}

// ---------------- launcher ----------------------------------------------------
extern "C" void kernel_launch(void* const* d_in, const int* in_sizes, int n_in,
                              void* d_out, int out_size) {
    const float* x  = (const float*)d_in[0];
    const int*   ei = (const int*)  d_in[1];
    const float* ew = (const float*)d_in[2];
    const int*   pi = (const int*)  d_in[3];
    const int*   eg = (const int*)  d_in[4];
    int base = (in_sizes[5] == 1) ? 6 : 5;
    const float* Wproj = (const float*)d_in[base + 0];
    const float* bproj = (const float*)d_in[base + 1];
    const float* W1    = (const float*)d_in[base + 2];
    const float* b1    = (const float*)d_in[base + 3];
    const float* W2    = (const float*)d_in[base + 4];
    const float* b2    = (const float*)d_in[base + 5];
    const float* Wa    = (const float*)d_in[base + 6];
    const float* ba    = (const float*)d_in[base + 7];
    const float* Wb    = (const float*)d_in[base + 8];
    const float* bb    = (const float*)d_in[base + 9];
    const float* Wc    = (const float*)d_in[base + 10];
    const float* bc    = (const float*)d_in[base + 11];

    int N  = in_sizes[0] / 64;
    int E  = in_sizes[2];
    int ES = in_sizes[4];
    const int G = GMAXC;

    float *bufA, *bufB, *bufC, *deg, *dinv, *logits, *gsum;
    unsigned* gmax;
    cudaGetSymbolAddress((void**)&bufA,   g_bufA);
    cudaGetSymbolAddress((void**)&bufB,   g_bufB);
    cudaGetSymbolAddress((void**)&bufC,   g_bufC);
    cudaGetSymbolAddress((void**)&deg,    g_deg);
    cudaGetSymbolAddress((void**)&dinv,   g_dinv);
    cudaGetSymbolAddress((void**)&logits, g_logits);
    cudaGetSymbolAddress((void**)&gmax,   g_gmax);
    cudaGetSymbolAddress((void**)&gsum,   g_gsum);

    const int* rowp = ei;        // edge_index[0]
    const int* colp = ei + E;    // edge_index[1]

    // degree + norm
    init_kernel<<<(N + 255) / 256, 256>>>(deg, gmax, gsum, N, G);
    deg_kernel<<<(E + 255) / 256, 256>>>(deg, colp, ew, E);
    dinv_kernel<<<(N + 255) / 256, 256>>>(deg, dinv, N);

    // h1 = x @ Wproj + bproj           [N,128] -> bufA
    dim3 gA((N + 63) / 64, 2);
    node_linear_kernel<<<gA, 256>>>(x, Wproj, bproj, bufA, N, 64, 128, 0);

    // hw1 = h1 @ W1                    [N,128] -> bufB
    node_linear_kernel<<<gA, 256>>>(bufA, W1, nullptr, bufB, N, 128, 128, 0);

    // agg1 = b1 + self + edge scatter  -> bufC
    agg_init_kernel<<<(N * 128 + 255) / 256, 256>>>(bufB, dinv, b1, bufC, N, 128);
    agg_edge_kernel<128><<<(E * 32 + 255) / 256, 256>>>(bufB, dinv, rowp, colp, ew, bufC, E);

    // hw2 = relu(agg1) @ W2            [N,64] -> bufA
    dim3 gB((N + 63) / 64, 1);
    node_linear_kernel<<<gB, 256>>>(bufC, W2, nullptr, bufA, N, 128, 64, 1);

    // agg2 = b2 + self + edge scatter  -> bufB  (= h3)
    agg_init_kernel<<<(N * 64 + 255) / 256, 256>>>(bufA, dinv, b2, bufB, N, 64);
    agg_edge_kernel<64><<<(E * 32 + 255) / 256, 256>>>(bufA, dinv, rowp, colp, ew, bufB, E);

    // hoisted pair-MLP layer A:  u0 = h3 @ Wa[0:64]   -> bufA (hw2 dead now)
    //                            u1 = h3 @ Wa[64:128] + ba -> bufC (agg1 dead now)
    node_linear_kernel<<<gB, 256>>>(bufB, Wa,           nullptr, bufA, N, 64, 64, 0);
    node_linear_kernel<<<gB, 256>>>(bufB, Wa + 64 * 64, ba,      bufC, N, 64, 64, 0);

    // pair MLP (gather+add+relu, 64->32->1) + segment softmax
    pair_mlp2_kernel<<<(ES + 255) / 256, 256>>>(bufA, bufC, pi, eg, Wb, bb, Wc, bc,
                                                logits, gmax, ES);
    softmax_exp_kernel<<<(ES + 255) / 256, 256>>>(logits, eg, gmax, gsum, ES);
    softmax_div_kernel<<<(ES + 255) / 256, 256>>>((float*)d_out, logits, eg, gsum, ES);
}